// round 10
// baseline (speedup 1.0000x reference)
#include <cuda_runtime.h>
#include <math.h>
#include <stdint.h>

#define BATCH 128
#define H0 128
#define W0 128
#define C1 16
#define H1 64
#define C2 32
#define H2 32
#define NCODES 512
#define DIM 32

typedef unsigned long long u64;

// Scratch (allocation-free rule: __device__ globals)
__device__ float g_h1[BATCH*C1*H1*H1];   // after conv1+pool+gelu  [B,16,64,64]
__device__ float g_h2[BATCH*C2*H2*H2];   // after conv2+pool       [B,32,32,32]
__device__ float g_g [BATCH*C1*H1*H1];   // after up+conv3+gelu    [B,16,64,64]
__device__ double g_loss;

__device__ __forceinline__ float gelu_exact(float v) {
    return 0.5f * v * (1.0f + erff(v * 0.70710678118654752440f));
}

// ---- packed fp32x2 helpers (Blackwell FFMA2 path) -------------------------
__device__ __forceinline__ u64 pk2(float lo, float hi) {
    u64 r; asm("mov.b64 %0, {%1,%2};" : "=l"(r) : "f"(lo), "f"(hi)); return r;
}
__device__ __forceinline__ void upk2(u64 v, float& lo, float& hi) {
    asm("mov.b64 {%0,%1}, %2;" : "=f"(lo), "=f"(hi) : "l"(v));
}
__device__ __forceinline__ u64 ffma2(u64 a, u64 b, u64 c) {
    u64 d; asm("fma.rn.f32x2 %0, %1, %2, %3;" : "=l"(d) : "l"(a), "l"(b), "l"(c)); return d;
}

// ---- legacy tensor-core helpers (sm_80+ ISA, works on plain sm_100) --------
__device__ __forceinline__ uint32_t f2tf32(float v) {
    uint32_t r; asm("cvt.rna.tf32.f32 %0, %1;" : "=r"(r) : "f"(v)); return r;
}
__device__ __forceinline__ void mma_tf32(float& d0, float& d1, float& d2, float& d3,
                                         uint32_t a0, uint32_t a1, uint32_t a2, uint32_t a3,
                                         uint32_t b0, uint32_t b1) {
    asm volatile(
        "mma.sync.aligned.m16n8k8.row.col.f32.tf32.tf32.f32 "
        "{%0,%1,%2,%3}, {%4,%5,%6,%7}, {%8,%9}, {%0,%1,%2,%3};"
        : "+f"(d0), "+f"(d1), "+f"(d2), "+f"(d3)
        : "r"(a0), "r"(a1), "r"(a2), "r"(a3), "r"(b0), "r"(b1));
}

// ---------------------------------------------------------------------------
// k1: conv1 (1->16, 3x3 SAME) + maxpool2 + gelu  (oc-paired f32x2)
// ---------------------------------------------------------------------------
__global__ __launch_bounds__(256) void k1(const float* __restrict__ x,
                                          const float* __restrict__ w1,
                                          const float* __restrict__ b1) {
    __shared__ __align__(16) float s_in[34*66];
    __shared__ __align__(16) float s_w[9*C1];     // [t][oc]
    __shared__ float s_b[C1];
    const int b = blockIdx.y;
    const int tile = blockIdx.x;
    const int px0 = (tile & 1) * 32;
    const int py0 = (tile >> 1) * 16;
    const int tid = threadIdx.x;
    if (tid < C1*9) { int oc = tid / 9, t = tid - oc*9; s_w[t*C1 + oc] = w1[tid]; }
    if (tid < C1)   s_b[tid] = b1[tid];
    const float* xim = x + b * (H0*W0);
    for (int i = tid; i < 34*66; i += 256) {
        int r = i / 66, c = i - r*66;
        int gy = 2*py0 - 1 + r;
        int gx = 2*px0 - 1 + c;
        float v = 0.f;
        if ((unsigned)gy < (unsigned)H0 && (unsigned)gx < (unsigned)W0)
            v = xim[gy*W0 + gx];
        s_in[i] = v;
    }
    __syncthreads();
    #pragma unroll 1
    for (int p = tid; p < 32*16; p += 256) {
        int py = p >> 5, px = p & 31;
        u64 up[4][4];
        #pragma unroll
        for (int i = 0; i < 4; i++) {
            float2 a = *(const float2*)&s_in[(2*py+i)*66 + 2*px];
            float2 c = *(const float2*)&s_in[(2*py+i)*66 + 2*px + 2];
            up[i][0] = pk2(a.x, a.x); up[i][1] = pk2(a.y, a.y);
            up[i][2] = pk2(c.x, c.x); up[i][3] = pk2(c.y, c.y);
        }
        u64 acc[8][4];
        #pragma unroll
        for (int op = 0; op < 8; op++)
            #pragma unroll
            for (int q = 0; q < 4; q++) acc[op][q] = 0ull;
        #pragma unroll
        for (int t = 0; t < 9; t++) {
            int ky = t / 3, kx = t - ky*3;
            ulonglong2 wA = *(const ulonglong2*)&s_w[t*C1 + 0];
            ulonglong2 wB = *(const ulonglong2*)&s_w[t*C1 + 4];
            ulonglong2 wC = *(const ulonglong2*)&s_w[t*C1 + 8];
            ulonglong2 wD = *(const ulonglong2*)&s_w[t*C1 + 12];
            u64 wv[8] = {wA.x, wA.y, wB.x, wB.y, wC.x, wC.y, wD.x, wD.y};
            #pragma unroll
            for (int op = 0; op < 8; op++)
                #pragma unroll
                for (int dy = 0; dy < 2; dy++)
                    #pragma unroll
                    for (int dx = 0; dx < 2; dx++)
                        acc[op][dy*2+dx] = ffma2(up[dy+ky][dx+kx], wv[op], acc[op][dy*2+dx]);
        }
        int gy = py0 + py, gx = px0 + px;
        #pragma unroll
        for (int op = 0; op < 8; op++) {
            float l0,h0,l1,h1,l2,h2,l3,h3;
            upk2(acc[op][0], l0, h0); upk2(acc[op][1], l1, h1);
            upk2(acc[op][2], l2, h2); upk2(acc[op][3], l3, h3);
            float mlo = fmaxf(fmaxf(l0,l1), fmaxf(l2,l3)) + s_b[op*2+0];
            float mhi = fmaxf(fmaxf(h0,h1), fmaxf(h2,h3)) + s_b[op*2+1];
            g_h1[((b*C1+op*2+0)*H1 + gy)*H1 + gx] = gelu_exact(mlo);
            g_h1[((b*C1+op*2+1)*H1 + gy)*H1 + gx] = gelu_exact(mhi);
        }
    }
}

// ---------------------------------------------------------------------------
// k2: conv2 (16->32, 3x3 SAME) + maxpool2  (oc-paired f32x2, 2 passes of 16 oc)
// ---------------------------------------------------------------------------
#define K2_SMEM ((16*18*66 + 16*9*32 + 32)*4)
__global__ __launch_bounds__(256) void k2(const float* __restrict__ w2,
                                          const float* __restrict__ b2) {
    extern __shared__ __align__(16) float sm2[];
    float* s_in = sm2;
    float* s_w  = sm2 + 16*18*66;      // [ic][t][oc]
    float* s_b  = s_w + 16*9*32;
    const int b = blockIdx.y;
    const int ry0 = blockIdx.x * 8;
    const int tid = threadIdx.x;
    for (int i = tid; i < 32*16*9; i += 256) {
        int o = i / 144; int rem = i - o*144; int ic = rem / 9; int t = rem - ic*9;
        s_w[(ic*9 + t)*32 + o] = w2[i];
    }
    if (tid < 32) s_b[tid] = b2[tid];
    for (int i = tid; i < 16*18*66; i += 256) {
        int ic = i / (18*66);
        int rem = i - ic*(18*66);
        int r = rem / 66, c = rem - r*66;
        int gy = 2*ry0 - 1 + r, gx = c - 1;
        float v = 0.f;
        if ((unsigned)gy < 64u && (unsigned)gx < 64u)
            v = g_h1[((b*16+ic)*64 + gy)*64 + gx];
        s_in[i] = v;
    }
    __syncthreads();
    const int py = tid >> 5, px = tid & 31;
    const int gy = ry0 + py, gx = px;
    #pragma unroll 1
    for (int pass = 0; pass < 2; pass++) {
        u64 acc[8][4];
        #pragma unroll
        for (int op = 0; op < 8; op++)
            #pragma unroll
            for (int q = 0; q < 4; q++) acc[op][q] = 0ull;
        #pragma unroll 1
        for (int ic = 0; ic < 16; ic++) {
            const float* base = &s_in[(ic*18 + 2*py)*66 + 2*px];
            u64 up[4][4];
            #pragma unroll
            for (int i = 0; i < 4; i++) {
                float2 a = *(const float2*)&base[i*66];
                float2 c = *(const float2*)&base[i*66 + 2];
                up[i][0] = pk2(a.x, a.x); up[i][1] = pk2(a.y, a.y);
                up[i][2] = pk2(c.x, c.x); up[i][3] = pk2(c.y, c.y);
            }
            #pragma unroll
            for (int t = 0; t < 9; t++) {
                int ky = t / 3, kx = t - ky*3;
                const float* wp = &s_w[(ic*9 + t)*32 + pass*16];
                ulonglong2 wA = *(const ulonglong2*)&wp[0];
                ulonglong2 wB = *(const ulonglong2*)&wp[4];
                ulonglong2 wC = *(const ulonglong2*)&wp[8];
                ulonglong2 wD = *(const ulonglong2*)&wp[12];
                u64 wv[8] = {wA.x, wA.y, wB.x, wB.y, wC.x, wC.y, wD.x, wD.y};
                #pragma unroll
                for (int op = 0; op < 8; op++)
                    #pragma unroll
                    for (int dy = 0; dy < 2; dy++)
                        #pragma unroll
                        for (int dx = 0; dx < 2; dx++)
                            acc[op][dy*2+dx] = ffma2(up[dy+ky][dx+kx], wv[op], acc[op][dy*2+dx]);
            }
        }
        #pragma unroll
        for (int op = 0; op < 8; op++) {
            float l0,h0,l1,h1,l2,h2,l3,h3;
            upk2(acc[op][0], l0, h0); upk2(acc[op][1], l1, h1);
            upk2(acc[op][2], l2, h2); upk2(acc[op][3], l3, h3);
            int oc = pass*16 + op*2;
            float mlo = fmaxf(fmaxf(l0,l1), fmaxf(l2,l3)) + s_b[oc+0];
            float mhi = fmaxf(fmaxf(h0,h1), fmaxf(h2,h3)) + s_b[oc+1];
            g_h2[((b*32+oc+0)*32 + gy)*32 + gx] = mlo;
            g_h2[((b*32+oc+1)*32 + gy)*32 + gx] = mhi;
        }
    }
}

// ---------------------------------------------------------------------------
// k3m: VQ mma.sync tf32, 3-split, 2-tile pipeline. NOW 128 px/block @512 thr:
// warp = 16-px strip (w>>1) x code half (w&1, 256 codes = 32 tiles). smem
// drops to ~188 KB so ONE k4 block (31 KB) co-resides per SM -> real overlap.
// 2-slot final reduce: half0 first on tie -> lower index (exact argmin).
// ---------------------------------------------------------------------------
#define ST36 36
#define O_CBH 0
#define O_CBL (NCODES*ST36)
#define O_ZH  (2*NCODES*ST36)
#define O_ZL  (O_ZH + 128*ST36)
#define O_CN2 (O_ZL + 128*ST36)
#define O_RE  (O_CN2 + NCODES)
#define O_RI  (O_RE + 256)
#define K3M_SMEM ((O_RI + 256)*4)

__global__ __launch_bounds__(512) void k3m(const float* __restrict__ codebook,
                                           float* __restrict__ out_idx) {
    extern __shared__ __align__(16) float smf[];
    uint32_t* smu = (uint32_t*)smf;
    const int tid = threadIdx.x;
    const int P0 = blockIdx.x * 128;       // 128 px, same image
    const int b  = P0 >> 10;
    const int n0 = P0 & 1023;

    // stage codebook hi/lo (tf32 split), stride 36
    for (int i = tid; i < NCODES*DIM; i += 512) {
        int k = i >> 5, d = i & 31;
        float v = codebook[i];
        uint32_t hb = f2tf32(v);
        float hf = __uint_as_float(hb);
        uint32_t lb = f2tf32(v - hf);
        smu[O_CBH + k*ST36 + d] = hb;
        smu[O_CBL + k*ST36 + d] = lb;
    }
    // stage z hi/lo (128 px)
    for (int i = tid; i < 128*DIM; i += 512) {
        int d = i >> 7, px = i & 127;
        float v = g_h2[(b*C2 + d)*1024 + n0 + px];
        uint32_t hb = f2tf32(v);
        float hf = __uint_as_float(hb);
        uint32_t lb = f2tf32(v - hf);
        smu[O_ZH + px*ST36 + d] = hb;
        smu[O_ZL + px*ST36 + d] = lb;
    }
    __syncthreads();
    // cn/2 from reconstructed hi+lo
    if (tid < NCODES) {
        float s = 0.f;
        #pragma unroll
        for (int d = 0; d < DIM; d++) {
            float c = smf[O_CBH + tid*ST36 + d] + smf[O_CBL + tid*ST36 + d];
            s = fmaf(c, c, s);
        }
        smf[O_CN2 + tid] = 0.5f * s;
    }
    __syncthreads();

    const int w = tid >> 5, lane = tid & 31;
    const int qr = lane >> 2, qc = lane & 3;
    const int strip = w >> 1, half = w & 1;
    const int m0 = strip * 16;               // 16-px strip

    // resident A fragments: z hi/lo for 4 k-steps
    uint32_t ah[4][4], al[4][4];
    #pragma unroll
    for (int kk = 0; kk < 4; kk++) {
        int kb = kk*8;
        const uint32_t* zh0 = &smu[O_ZH + (m0+qr)*ST36 + kb + qc];
        const uint32_t* zh8 = &smu[O_ZH + (m0+qr+8)*ST36 + kb + qc];
        const uint32_t* zl0 = &smu[O_ZL + (m0+qr)*ST36 + kb + qc];
        const uint32_t* zl8 = &smu[O_ZL + (m0+qr+8)*ST36 + kb + qc];
        ah[kk][0] = zh0[0]; ah[kk][1] = zh8[0]; ah[kk][2] = zh0[4]; ah[kk][3] = zh8[4];
        al[kk][0] = zl0[0]; al[kk][1] = zl8[0]; al[kk][2] = zl0[4]; al[kk][3] = zl8[4];
    }

    float bestA = 3.4e38f, bestB = 3.4e38f;
    int biA = 0, biB = 0;
    const int tbase = half * 32;              // 32 tiles = 256 codes per warp

    #pragma unroll 1
    for (int tt = 0; tt < 32; tt += 2) {
        const int c0 = (tbase + tt) * 8;
        const int c1 = c0 + 8;
        const uint32_t* xbh = &smu[O_CBH + (c0+qr)*ST36 + qc];
        const uint32_t* xbl = &smu[O_CBL + (c0+qr)*ST36 + qc];
        const uint32_t* ybh = &smu[O_CBH + (c1+qr)*ST36 + qc];
        const uint32_t* ybl = &smu[O_CBL + (c1+qr)*ST36 + qc];
        uint32_t xh[8], xl[8], yh[8], yl[8];
        #pragma unroll
        for (int kk = 0; kk < 4; kk++) {
            xh[kk*2] = xbh[kk*8]; xh[kk*2+1] = xbh[kk*8+4];
            xl[kk*2] = xbl[kk*8]; xl[kk*2+1] = xbl[kk*8+4];
            yh[kk*2] = ybh[kk*8]; yh[kk*2+1] = ybh[kk*8+4];
            yl[kk*2] = ybl[kk*8]; yl[kk*2+1] = ybl[kk*8+4];
        }
        float xhh0=0.f,xhh1=0.f,xhh2=0.f,xhh3=0.f;
        float xhl0=0.f,xhl1=0.f,xhl2=0.f,xhl3=0.f;
        float xlh0=0.f,xlh1=0.f,xlh2=0.f,xlh3=0.f;
        float yhh0=0.f,yhh1=0.f,yhh2=0.f,yhh3=0.f;
        float yhl0=0.f,yhl1=0.f,yhl2=0.f,yhl3=0.f;
        float ylh0=0.f,ylh1=0.f,ylh2=0.f,ylh3=0.f;
        #pragma unroll
        for (int kk = 0; kk < 4; kk++) {
            mma_tf32(xhh0,xhh1,xhh2,xhh3, ah[kk][0],ah[kk][1],ah[kk][2],ah[kk][3], xh[kk*2],xh[kk*2+1]);
            mma_tf32(yhh0,yhh1,yhh2,yhh3, ah[kk][0],ah[kk][1],ah[kk][2],ah[kk][3], yh[kk*2],yh[kk*2+1]);
            mma_tf32(xhl0,xhl1,xhl2,xhl3, ah[kk][0],ah[kk][1],ah[kk][2],ah[kk][3], xl[kk*2],xl[kk*2+1]);
            mma_tf32(yhl0,yhl1,yhl2,yhl3, ah[kk][0],ah[kk][1],ah[kk][2],ah[kk][3], yl[kk*2],yl[kk*2+1]);
            mma_tf32(xlh0,xlh1,xlh2,xlh3, al[kk][0],al[kk][1],al[kk][2],al[kk][3], xh[kk*2],xh[kk*2+1]);
            mma_tf32(ylh0,ylh1,ylh2,ylh3, al[kk][0],al[kk][1],al[kk][2],al[kk][3], yh[kk*2],yh[kk*2+1]);
        }
        {
            float d0 = xhh0 + (xhl0 + xlh0);
            float d1 = xhh1 + (xhl1 + xlh1);
            float d2 = xhh2 + (xhl2 + xlh2);
            float d3 = xhh3 + (xhl3 + xlh3);
            const int ce = c0 + 2*qc;
            float cnE = smf[O_CN2 + ce], cnO = smf[O_CN2 + ce + 1];
            float e;
            e = cnE - d0; if (e < bestA) { bestA = e; biA = ce; }
            e = cnO - d1; if (e < bestA) { bestA = e; biA = ce + 1; }
            e = cnE - d2; if (e < bestB) { bestB = e; biB = ce; }
            e = cnO - d3; if (e < bestB) { bestB = e; biB = ce + 1; }
        }
        {
            float d0 = yhh0 + (yhl0 + ylh0);
            float d1 = yhh1 + (yhl1 + ylh1);
            float d2 = yhh2 + (yhl2 + ylh2);
            float d3 = yhh3 + (yhl3 + ylh3);
            const int ce = c1 + 2*qc;
            float cnE = smf[O_CN2 + ce], cnO = smf[O_CN2 + ce + 1];
            float e;
            e = cnE - d0; if (e < bestA) { bestA = e; biA = ce; }
            e = cnO - d1; if (e < bestA) { bestA = e; biA = ce + 1; }
            e = cnE - d2; if (e < bestB) { bestB = e; biB = ce; }
            e = cnO - d3; if (e < bestB) { bestB = e; biB = ce + 1; }
        }
    }
    // quad reduce across qc (exact: tie -> smaller index)
    #pragma unroll
    for (int off = 1; off <= 2; off <<= 1) {
        float eA = __shfl_xor_sync(0xffffffffu, bestA, off);
        int   iA = __shfl_xor_sync(0xffffffffu, biA, off);
        if (eA < bestA || (eA == bestA && iA < biA)) { bestA = eA; biA = iA; }
        float eB = __shfl_xor_sync(0xffffffffu, bestB, off);
        int   iB = __shfl_xor_sync(0xffffffffu, biB, off);
        if (eB < bestB || (eB == bestB && iB < biB)) { bestB = eB; biB = iB; }
    }
    float* s_re = &smf[O_RE];
    int*   s_ri = (int*)&smf[O_RI];
    if (qc == 0) {
        s_re[half*128 + m0 + qr]     = bestA;
        s_ri[half*128 + m0 + qr]     = biA;
        s_re[half*128 + m0 + 8 + qr] = bestB;
        s_ri[half*128 + m0 + 8 + qr] = biB;
    }
    __syncthreads();

    // final combine over 2 halves + commit loss (exact, hi+lo-consistent)
    float cl = 0.f;
    if (tid < 128) {
        float e0 = s_re[tid], e1 = s_re[128 + tid];
        int   i0 = s_ri[tid], i1 = s_ri[128 + tid];
        int fi = (e1 < e0) ? i1 : i0;   // tie -> half0 = lower index, exact
        out_idx[P0 + tid] = (float)fi;
        #pragma unroll
        for (int d = 0; d < DIM; d++) {
            float zv = smf[O_ZH + tid*ST36 + d] + smf[O_ZL + tid*ST36 + d];
            float cv = smf[O_CBH + fi*ST36 + d] + smf[O_CBL + fi*ST36 + d];
            float df = cv - zv;
            cl = fmaf(df, df, cl);
        }
    }
    #pragma unroll
    for (int off = 16; off; off >>= 1) cl += __shfl_down_sync(0xffffffffu, cl, off);
    __shared__ float wsum[16];
    if ((tid & 31) == 0) wsum[tid >> 5] = (tid < 128) ? cl : 0.f;
    __syncthreads();
    if (tid == 0) {
        float s = wsum[0] + wsum[1] + wsum[2] + wsum[3];
        atomicAdd(&g_loss, (double)s);
    }
}

// ---------------------------------------------------------------------------
// k4: nearest-upsample2(h2) + conv3 (32->16, 3x3 SAME) + gelu
// NOW 16x16 output tile, 1 px/thread: smem 31.3 KB, ~60 regs -> co-resides
// with one k3m block per SM. 4 distinct u values per ic (upsample dedup).
// ---------------------------------------------------------------------------
#define K4_SMEM ((32*10*10 + 32*9*16 + 16)*4)
__global__ __launch_bounds__(256) void k4(const float* __restrict__ w3,
                                          const float* __restrict__ b3) {
    extern __shared__ __align__(16) float sm4[];
    float* s_h = sm4;                 // [32][10][10]
    float* s_w = sm4 + 32*100;        // [ic][t][oc=16]
    float* s_b = s_w + 32*9*16;
    const int b = blockIdx.y;
    const int tile = blockIdx.x;      // 16 tiles: 4x4 of 16x16
    const int oy = (tile >> 2) * 16, ox = (tile & 3) * 16;
    const int hy0 = oy/2 - 1, hx0 = ox/2 - 1;
    const int tid = threadIdx.x;
    for (int i = tid; i < 16*32*9; i += 256) {
        int o = i / 288; int rem = i - o*288; int ic = rem / 9; int t = rem - ic*9;
        s_w[(ic*9 + t)*16 + o] = w3[i];
    }
    if (tid < 16) s_b[tid] = b3[tid];
    for (int i = tid; i < 32*100; i += 256) {
        int ic = i / 100;
        int rem = i - ic*100;
        int r = rem / 10, c = rem - r*10;
        int hy = hy0 + r, hx = hx0 + c;
        float v = 0.f;
        if ((unsigned)hy < 32u && (unsigned)hx < 32u)
            v = g_h2[((b*32+ic)*32 + hy)*32 + hx];
        s_h[i] = v;
    }
    __syncthreads();
    const int py = tid >> 4, px = tid & 15;
    const int y0 = oy + py, x0 = ox + px;
    // 2 distinct input rows/cols per output px (nearest-up2 dedup)
    const int r0 = ((y0 - 1) >> 1) - hy0;
    const int r1 = ((y0 + 1) >> 1) - hy0;
    const int c0 = ((x0 - 1) >> 1) - hx0;
    const int c1 = ((x0 + 1) >> 1) - hx0;
    // ky/kx (0..2) -> which of the two rows/cols
    const int amap1 = (y0 & 1) ? 0 : 1;   // middle tap row
    const int bmap1 = (x0 & 1) ? 0 : 1;
    int ar[3]; ar[0] = r0; ar[1] = amap1 ? r1 : r0; ar[2] = r1;
    int bc[3]; bc[0] = c0; bc[1] = bmap1 ? c1 : c0; bc[2] = c1;
    // fix middle: ar[1] = (y0&1)? r0 : r1
    ar[1] = (y0 & 1) ? r0 : r1;
    bc[1] = (x0 & 1) ? c0 : c1;

    u64 acc[8];
    #pragma unroll
    for (int op = 0; op < 8; op++) acc[op] = 0ull;
    #pragma unroll 1
    for (int ic = 0; ic < 32; ic++) {
        const float* hbase = &s_h[ic*100];
        float u00 = hbase[r0*10 + c0], u01 = hbase[r0*10 + c1];
        float u10 = hbase[r1*10 + c0], u11 = hbase[r1*10 + c1];
        u64 up[2][2];
        up[0][0] = pk2(u00, u00); up[0][1] = pk2(u01, u01);
        up[1][0] = pk2(u10, u10); up[1][1] = pk2(u11, u11);
        #pragma unroll
        for (int t = 0; t < 9; t++) {
            int ky = t / 3, kx = t - ky*3;
            int ai = (ky == 0) ? 0 : (ky == 2) ? 1 : ((y0 & 1) ? 0 : 1);
            int bi = (kx == 0) ? 0 : (kx == 2) ? 1 : ((x0 & 1) ? 0 : 1);
            u64 uv = up[ai][bi];
            const float* wp = &s_w[(ic*9 + t)*16];
            ulonglong2 wA = *(const ulonglong2*)&wp[0];
            ulonglong2 wB = *(const ulonglong2*)&wp[4];
            ulonglong2 wC = *(const ulonglong2*)&wp[8];
            ulonglong2 wD = *(const ulonglong2*)&wp[12];
            acc[0] = ffma2(uv, wA.x, acc[0]);
            acc[1] = ffma2(uv, wA.y, acc[1]);
            acc[2] = ffma2(uv, wB.x, acc[2]);
            acc[3] = ffma2(uv, wB.y, acc[3]);
            acc[4] = ffma2(uv, wC.x, acc[4]);
            acc[5] = ffma2(uv, wC.y, acc[5]);
            acc[6] = ffma2(uv, wD.x, acc[6]);
            acc[7] = ffma2(uv, wD.y, acc[7]);
        }
    }
    #pragma unroll
    for (int op = 0; op < 8; op++) {
        int oc = op*2;
        float lo, hi;
        upk2(acc[op], lo, hi);
        g_g[((b*16+oc+0)*64 + y0)*64 + x0] = gelu_exact(lo + s_b[oc+0]);
        g_g[((b*16+oc+1)*64 + y0)*64 + x0] = gelu_exact(hi + s_b[oc+1]);
    }
}

// ---------------------------------------------------------------------------
// k5: nearest-upsample2(g) + conv4 (16->1, 3x3 SAME) + clip
// ---------------------------------------------------------------------------
__global__ __launch_bounds__(256) void k5(const float* __restrict__ w4,
                                          const float* __restrict__ b4,
                                          float* __restrict__ out) {
    __shared__ float s_g[16*18*18];
    __shared__ float s_w[144];
    __shared__ float s_bb[1];
    const int b = blockIdx.y;
    const int tile = blockIdx.x;
    const int oy = (tile >> 2) * 32, ox = (tile & 3) * 32;
    const int gy0 = oy/2 - 1, gx0 = ox/2 - 1;
    const int tid = threadIdx.y*16 + threadIdx.x;
    if (tid < 144) s_w[tid] = w4[tid];
    if (tid == 0) s_bb[0] = b4[0];
    for (int i = tid; i < 16*18*18; i += 256) {
        int ic = i / 324;
        int rem = i - ic*324;
        int r = rem / 18, c = rem - r*18;
        int gy = gy0 + r, gx = gx0 + c;
        float v = 0.f;
        if ((unsigned)gy < 64u && (unsigned)gx < 64u)
            v = g_g[((b*16+ic)*64 + gy)*64 + gx];
        s_g[i] = v;
    }
    __syncthreads();
    const int ty = threadIdx.y, tx = threadIdx.x;
    const int y0 = oy + 2*ty, x0 = ox + 2*tx;
    const int map[4] = {0, 1, 1, 2};
    float acc[4] = {0.f, 0.f, 0.f, 0.f};
    #pragma unroll 1
    for (int ic = 0; ic < 16; ic++) {
        float v[3][3];
        #pragma unroll
        for (int a = 0; a < 3; a++)
            #pragma unroll
            for (int c = 0; c < 3; c++)
                v[a][c] = s_g[(ic*18 + ty + a)*18 + tx + c];
        const float* w = &s_w[ic*9];
        #pragma unroll
        for (int t = 0; t < 9; t++) {
            int ky = t / 3, kx = t - ky*3;
            float wt = w[t];
            #pragma unroll
            for (int dy = 0; dy < 2; dy++)
                #pragma unroll
                for (int dx = 0; dx < 2; dx++)
                    acc[dy*2+dx] = fmaf(wt, v[map[dy+ky]][map[dx+kx]], acc[dy*2+dx]);
        }
    }
    float bb = s_bb[0];
    #pragma unroll
    for (int dy = 0; dy < 2; dy++)
        #pragma unroll
        for (int dx = 0; dx < 2; dx++) {
            float v = fminf(fmaxf(acc[dy*2+dx] + bb, -1.f), 1.f);
            out[(b*H0 + (y0+dy))*W0 + (x0+dx)] = v;
        }
}

// ---------------------------------------------------------------------------
__global__ void k_zero() { if (threadIdx.x == 0) g_loss = 0.0; }
__global__ void k_fin(float* __restrict__ out_loss) {
    if (threadIdx.x == 0)
        out_loss[0] = (float)(g_loss / (double)(BATCH * 1024 * DIM));
}

// ---------------------------------------------------------------------------
extern "C" void kernel_launch(void* const* d_in, const int* in_sizes, int n_in,
                              void* d_out, int out_size) {
    const float* x  = (const float*)d_in[0];
    const float* w1 = (const float*)d_in[1];
    const float* b1 = (const float*)d_in[2];
    const float* w2 = (const float*)d_in[3];
    const float* b2 = (const float*)d_in[4];
    const float* cb = (const float*)d_in[5];
    const float* w3 = (const float*)d_in[6];
    const float* b3 = (const float*)d_in[7];
    const float* w4 = (const float*)d_in[8];
    const float* b4 = (const float*)d_in[9];

    float* out      = (float*)d_out;
    float* out_idx  = out + BATCH*H0*W0;          // 2,097,152
    float* out_loss = out_idx + BATCH*H2*H2;      // +131,072

    cudaFuncSetAttribute(k2,  cudaFuncAttributeMaxDynamicSharedMemorySize, K2_SMEM);
    cudaFuncSetAttribute(k3m, cudaFuncAttributeMaxDynamicSharedMemorySize, K3M_SMEM);
    cudaFuncSetAttribute(k4,  cudaFuncAttributeMaxDynamicSharedMemorySize, K4_SMEM);

    cudaStream_t s2;
    cudaEvent_t evFork, evJoin;
    cudaStreamCreateWithFlags(&s2, cudaStreamNonBlocking);
    cudaEventCreateWithFlags(&evFork, cudaEventDisableTiming);
    cudaEventCreateWithFlags(&evJoin, cudaEventDisableTiming);

    // main chain
    k_zero<<<1, 32>>>();
    k1<<<dim3(8, BATCH), 256>>>(x, w1, b1);
    k2<<<dim3(4, BATCH), 256, K2_SMEM>>>(w2, b2);

    // fork: VQ on side stream (tensor pipe), decoder on main stream (fma pipe)
    // k3m (188 KB) + k4 (31 KB) now co-reside per SM -> true pipe-level overlap
    cudaEventRecord(evFork, 0);
    cudaStreamWaitEvent(s2, evFork, 0);
    k3m<<<1024, 512, K3M_SMEM, s2>>>(cb, out_idx);
    cudaEventRecord(evJoin, s2);

    k4<<<dim3(16, BATCH), 256, K4_SMEM>>>(w3, b3);
    k5<<<dim3(16, BATCH), dim3(16,16)>>>(w4, b4, out);

    cudaStreamWaitEvent(0, evJoin, 0);
    k_fin<<<1, 32>>>(out_loss);
}

// round 11
// speedup vs baseline: 1.3518x; 1.3518x over previous
#include <cuda_runtime.h>
#include <math.h>
#include <stdint.h>

#define BATCH 128
#define HALFB 64
#define H0 128
#define W0 128
#define C1 16
#define H1 64
#define C2 32
#define H2 32
#define NCODES 512
#define DIM 32

typedef unsigned long long u64;

// Scratch (allocation-free rule: __device__ globals)
__device__ float g_h1[BATCH*C1*H1*H1];   // after conv1+pool+gelu  [B,16,64,64]
__device__ float g_h2[BATCH*C2*H2*H2];   // after conv2+pool       [B,32,32,32]
__device__ float g_g [BATCH*C1*H1*H1];   // after up+conv3+gelu    [B,16,64,64]
__device__ double g_loss;

__device__ __forceinline__ float gelu_exact(float v) {
    return 0.5f * v * (1.0f + erff(v * 0.70710678118654752440f));
}

// ---- packed fp32x2 helpers (Blackwell FFMA2 path) -------------------------
__device__ __forceinline__ u64 pk2(float lo, float hi) {
    u64 r; asm("mov.b64 %0, {%1,%2};" : "=l"(r) : "f"(lo), "f"(hi)); return r;
}
__device__ __forceinline__ void upk2(u64 v, float& lo, float& hi) {
    asm("mov.b64 {%0,%1}, %2;" : "=f"(lo), "=f"(hi) : "l"(v));
}
__device__ __forceinline__ u64 ffma2(u64 a, u64 b, u64 c) {
    u64 d; asm("fma.rn.f32x2 %0, %1, %2, %3;" : "=l"(d) : "l"(a), "l"(b), "l"(c)); return d;
}

// ---- legacy tensor-core helpers (sm_80+ ISA, works on plain sm_100) --------
__device__ __forceinline__ uint32_t f2tf32(float v) {
    uint32_t r; asm("cvt.rna.tf32.f32 %0, %1;" : "=r"(r) : "f"(v)); return r;
}
__device__ __forceinline__ void mma_tf32(float& d0, float& d1, float& d2, float& d3,
                                         uint32_t a0, uint32_t a1, uint32_t a2, uint32_t a3,
                                         uint32_t b0, uint32_t b1) {
    asm volatile(
        "mma.sync.aligned.m16n8k8.row.col.f32.tf32.tf32.f32 "
        "{%0,%1,%2,%3}, {%4,%5,%6,%7}, {%8,%9}, {%0,%1,%2,%3};"
        : "+f"(d0), "+f"(d1), "+f"(d2), "+f"(d3)
        : "r"(a0), "r"(a1), "r"(a2), "r"(a3), "r"(b0), "r"(b1));
}

// ---------------------------------------------------------------------------
// k1: conv1 (1->16, 3x3 SAME) + maxpool2 + gelu  (oc-paired f32x2)
// grid (8, HALFB); batch offset b0
// ---------------------------------------------------------------------------
__global__ __launch_bounds__(256) void k1(const float* __restrict__ x,
                                          const float* __restrict__ w1,
                                          const float* __restrict__ b1, int b0) {
    __shared__ __align__(16) float s_in[34*66];
    __shared__ __align__(16) float s_w[9*C1];     // [t][oc]
    __shared__ float s_b[C1];
    const int b = blockIdx.y + b0;
    const int tile = blockIdx.x;
    const int px0 = (tile & 1) * 32;
    const int py0 = (tile >> 1) * 16;
    const int tid = threadIdx.x;
    if (tid < C1*9) { int oc = tid / 9, t = tid - oc*9; s_w[t*C1 + oc] = w1[tid]; }
    if (tid < C1)   s_b[tid] = b1[tid];
    const float* xim = x + b * (H0*W0);
    for (int i = tid; i < 34*66; i += 256) {
        int r = i / 66, c = i - r*66;
        int gy = 2*py0 - 1 + r;
        int gx = 2*px0 - 1 + c;
        float v = 0.f;
        if ((unsigned)gy < (unsigned)H0 && (unsigned)gx < (unsigned)W0)
            v = xim[gy*W0 + gx];
        s_in[i] = v;
    }
    __syncthreads();
    #pragma unroll 1
    for (int p = tid; p < 32*16; p += 256) {
        int py = p >> 5, px = p & 31;
        u64 up[4][4];
        #pragma unroll
        for (int i = 0; i < 4; i++) {
            float2 a = *(const float2*)&s_in[(2*py+i)*66 + 2*px];
            float2 c = *(const float2*)&s_in[(2*py+i)*66 + 2*px + 2];
            up[i][0] = pk2(a.x, a.x); up[i][1] = pk2(a.y, a.y);
            up[i][2] = pk2(c.x, c.x); up[i][3] = pk2(c.y, c.y);
        }
        u64 acc[8][4];
        #pragma unroll
        for (int op = 0; op < 8; op++)
            #pragma unroll
            for (int q = 0; q < 4; q++) acc[op][q] = 0ull;
        #pragma unroll
        for (int t = 0; t < 9; t++) {
            int ky = t / 3, kx = t - ky*3;
            ulonglong2 wA = *(const ulonglong2*)&s_w[t*C1 + 0];
            ulonglong2 wB = *(const ulonglong2*)&s_w[t*C1 + 4];
            ulonglong2 wC = *(const ulonglong2*)&s_w[t*C1 + 8];
            ulonglong2 wD = *(const ulonglong2*)&s_w[t*C1 + 12];
            u64 wv[8] = {wA.x, wA.y, wB.x, wB.y, wC.x, wC.y, wD.x, wD.y};
            #pragma unroll
            for (int op = 0; op < 8; op++)
                #pragma unroll
                for (int dy = 0; dy < 2; dy++)
                    #pragma unroll
                    for (int dx = 0; dx < 2; dx++)
                        acc[op][dy*2+dx] = ffma2(up[dy+ky][dx+kx], wv[op], acc[op][dy*2+dx]);
        }
        int gy = py0 + py, gx = px0 + px;
        #pragma unroll
        for (int op = 0; op < 8; op++) {
            float l0,h0,l1,h1,l2,h2,l3,h3;
            upk2(acc[op][0], l0, h0); upk2(acc[op][1], l1, h1);
            upk2(acc[op][2], l2, h2); upk2(acc[op][3], l3, h3);
            float mlo = fmaxf(fmaxf(l0,l1), fmaxf(l2,l3)) + s_b[op*2+0];
            float mhi = fmaxf(fmaxf(h0,h1), fmaxf(h2,h3)) + s_b[op*2+1];
            g_h1[((b*C1+op*2+0)*H1 + gy)*H1 + gx] = gelu_exact(mlo);
            g_h1[((b*C1+op*2+1)*H1 + gy)*H1 + gx] = gelu_exact(mhi);
        }
    }
}

// ---------------------------------------------------------------------------
// k2: conv2 (16->32, 3x3 SAME) + maxpool2  (oc-paired f32x2, 2 passes of 16 oc)
// grid (4, HALFB); batch offset b0
// ---------------------------------------------------------------------------
#define K2_SMEM ((16*18*66 + 16*9*32 + 32)*4)
__global__ __launch_bounds__(256) void k2(const float* __restrict__ w2,
                                          const float* __restrict__ b2, int b0) {
    extern __shared__ __align__(16) float sm2[];
    float* s_in = sm2;
    float* s_w  = sm2 + 16*18*66;      // [ic][t][oc]
    float* s_b  = s_w + 16*9*32;
    const int b = blockIdx.y + b0;
    const int ry0 = blockIdx.x * 8;
    const int tid = threadIdx.x;
    for (int i = tid; i < 32*16*9; i += 256) {
        int o = i / 144; int rem = i - o*144; int ic = rem / 9; int t = rem - ic*9;
        s_w[(ic*9 + t)*32 + o] = w2[i];
    }
    if (tid < 32) s_b[tid] = b2[tid];
    for (int i = tid; i < 16*18*66; i += 256) {
        int ic = i / (18*66);
        int rem = i - ic*(18*66);
        int r = rem / 66, c = rem - r*66;
        int gy = 2*ry0 - 1 + r, gx = c - 1;
        float v = 0.f;
        if ((unsigned)gy < 64u && (unsigned)gx < 64u)
            v = g_h1[((b*16+ic)*64 + gy)*64 + gx];
        s_in[i] = v;
    }
    __syncthreads();
    const int py = tid >> 5, px = tid & 31;
    const int gy = ry0 + py, gx = px;
    #pragma unroll 1
    for (int pass = 0; pass < 2; pass++) {
        u64 acc[8][4];
        #pragma unroll
        for (int op = 0; op < 8; op++)
            #pragma unroll
            for (int q = 0; q < 4; q++) acc[op][q] = 0ull;
        #pragma unroll 1
        for (int ic = 0; ic < 16; ic++) {
            const float* base = &s_in[(ic*18 + 2*py)*66 + 2*px];
            u64 up[4][4];
            #pragma unroll
            for (int i = 0; i < 4; i++) {
                float2 a = *(const float2*)&base[i*66];
                float2 c = *(const float2*)&base[i*66 + 2];
                up[i][0] = pk2(a.x, a.x); up[i][1] = pk2(a.y, a.y);
                up[i][2] = pk2(c.x, c.x); up[i][3] = pk2(c.y, c.y);
            }
            #pragma unroll
            for (int t = 0; t < 9; t++) {
                int ky = t / 3, kx = t - ky*3;
                const float* wp = &s_w[(ic*9 + t)*32 + pass*16];
                ulonglong2 wA = *(const ulonglong2*)&wp[0];
                ulonglong2 wB = *(const ulonglong2*)&wp[4];
                ulonglong2 wC = *(const ulonglong2*)&wp[8];
                ulonglong2 wD = *(const ulonglong2*)&wp[12];
                u64 wv[8] = {wA.x, wA.y, wB.x, wB.y, wC.x, wC.y, wD.x, wD.y};
                #pragma unroll
                for (int op = 0; op < 8; op++)
                    #pragma unroll
                    for (int dy = 0; dy < 2; dy++)
                        #pragma unroll
                        for (int dx = 0; dx < 2; dx++)
                            acc[op][dy*2+dx] = ffma2(up[dy+ky][dx+kx], wv[op], acc[op][dy*2+dx]);
            }
        }
        #pragma unroll
        for (int op = 0; op < 8; op++) {
            float l0,h0,l1,h1,l2,h2,l3,h3;
            upk2(acc[op][0], l0, h0); upk2(acc[op][1], l1, h1);
            upk2(acc[op][2], l2, h2); upk2(acc[op][3], l3, h3);
            int oc = pass*16 + op*2;
            float mlo = fmaxf(fmaxf(l0,l1), fmaxf(l2,l3)) + s_b[oc+0];
            float mhi = fmaxf(fmaxf(h0,h1), fmaxf(h2,h3)) + s_b[oc+1];
            g_h2[((b*32+oc+0)*32 + gy)*32 + gx] = mlo;
            g_h2[((b*32+oc+1)*32 + gy)*32 + gx] = mhi;
        }
    }
}

// ---------------------------------------------------------------------------
// k3m: (R9 version) VQ mma.sync tf32, 3-split, 2-tile pipeline.
// 512 threads, 256 px/block; warp = 16-px strip x all 512 codes (64 tiles).
// grid 128 per half; pixel offset p0ofs = b0*1024.
// ---------------------------------------------------------------------------
#define ST36 36
#define O_CBH 0
#define O_CBL (NCODES*ST36)
#define O_ZH  (2*NCODES*ST36)
#define O_ZL  (O_ZH + 256*ST36)
#define O_CN2 (O_ZL + 256*ST36)
#define O_RI  (O_CN2 + NCODES)
#define K3M_SMEM ((O_RI + 256)*4)

__global__ __launch_bounds__(512) void k3m(const float* __restrict__ codebook,
                                           float* __restrict__ out_idx, int p0ofs) {
    extern __shared__ __align__(16) float smf[];
    uint32_t* smu = (uint32_t*)smf;
    const int tid = threadIdx.x;
    const int P0 = p0ofs + blockIdx.x * 256;   // 256 px, same image
    const int b  = P0 >> 10;
    const int n0 = P0 & 1023;

    for (int i = tid; i < NCODES*DIM; i += 512) {
        int k = i >> 5, d = i & 31;
        float v = codebook[i];
        uint32_t hb = f2tf32(v);
        float hf = __uint_as_float(hb);
        uint32_t lb = f2tf32(v - hf);
        smu[O_CBH + k*ST36 + d] = hb;
        smu[O_CBL + k*ST36 + d] = lb;
    }
    for (int i = tid; i < 256*DIM; i += 512) {
        int d = i >> 8, px = i & 255;
        float v = g_h2[(b*C2 + d)*1024 + n0 + px];
        uint32_t hb = f2tf32(v);
        float hf = __uint_as_float(hb);
        uint32_t lb = f2tf32(v - hf);
        smu[O_ZH + px*ST36 + d] = hb;
        smu[O_ZL + px*ST36 + d] = lb;
    }
    __syncthreads();
    if (tid < NCODES) {
        float s = 0.f;
        #pragma unroll
        for (int d = 0; d < DIM; d++) {
            float c = smf[O_CBH + tid*ST36 + d] + smf[O_CBL + tid*ST36 + d];
            s = fmaf(c, c, s);
        }
        smf[O_CN2 + tid] = 0.5f * s;
    }
    __syncthreads();

    const int w = tid >> 5, lane = tid & 31;
    const int qr = lane >> 2, qc = lane & 3;
    const int m0 = w * 16;

    uint32_t ah[4][4], al[4][4];
    #pragma unroll
    for (int kk = 0; kk < 4; kk++) {
        int kb = kk*8;
        const uint32_t* zh0 = &smu[O_ZH + (m0+qr)*ST36 + kb + qc];
        const uint32_t* zh8 = &smu[O_ZH + (m0+qr+8)*ST36 + kb + qc];
        const uint32_t* zl0 = &smu[O_ZL + (m0+qr)*ST36 + kb + qc];
        const uint32_t* zl8 = &smu[O_ZL + (m0+qr+8)*ST36 + kb + qc];
        ah[kk][0] = zh0[0]; ah[kk][1] = zh8[0]; ah[kk][2] = zh0[4]; ah[kk][3] = zh8[4];
        al[kk][0] = zl0[0]; al[kk][1] = zl8[0]; al[kk][2] = zl0[4]; al[kk][3] = zl8[4];
    }

    float bestA = 3.4e38f, bestB = 3.4e38f;
    int biA = 0, biB = 0;

    #pragma unroll 1
    for (int t = 0; t < 64; t += 2) {
        const int c0 = t * 8;
        const int c1 = c0 + 8;
        const uint32_t* xbh = &smu[O_CBH + (c0+qr)*ST36 + qc];
        const uint32_t* xbl = &smu[O_CBL + (c0+qr)*ST36 + qc];
        const uint32_t* ybh = &smu[O_CBH + (c1+qr)*ST36 + qc];
        const uint32_t* ybl = &smu[O_CBL + (c1+qr)*ST36 + qc];
        uint32_t xh[8], xl[8], yh[8], yl[8];
        #pragma unroll
        for (int kk = 0; kk < 4; kk++) {
            xh[kk*2] = xbh[kk*8]; xh[kk*2+1] = xbh[kk*8+4];
            xl[kk*2] = xbl[kk*8]; xl[kk*2+1] = xbl[kk*8+4];
            yh[kk*2] = ybh[kk*8]; yh[kk*2+1] = ybh[kk*8+4];
            yl[kk*2] = ybl[kk*8]; yl[kk*2+1] = ybl[kk*8+4];
        }
        float xhh0=0.f,xhh1=0.f,xhh2=0.f,xhh3=0.f;
        float xhl0=0.f,xhl1=0.f,xhl2=0.f,xhl3=0.f;
        float xlh0=0.f,xlh1=0.f,xlh2=0.f,xlh3=0.f;
        float yhh0=0.f,yhh1=0.f,yhh2=0.f,yhh3=0.f;
        float yhl0=0.f,yhl1=0.f,yhl2=0.f,yhl3=0.f;
        float ylh0=0.f,ylh1=0.f,ylh2=0.f,ylh3=0.f;
        #pragma unroll
        for (int kk = 0; kk < 4; kk++) {
            mma_tf32(xhh0,xhh1,xhh2,xhh3, ah[kk][0],ah[kk][1],ah[kk][2],ah[kk][3], xh[kk*2],xh[kk*2+1]);
            mma_tf32(yhh0,yhh1,yhh2,yhh3, ah[kk][0],ah[kk][1],ah[kk][2],ah[kk][3], yh[kk*2],yh[kk*2+1]);
            mma_tf32(xhl0,xhl1,xhl2,xhl3, ah[kk][0],ah[kk][1],ah[kk][2],ah[kk][3], xl[kk*2],xl[kk*2+1]);
            mma_tf32(yhl0,yhl1,yhl2,yhl3, ah[kk][0],ah[kk][1],ah[kk][2],ah[kk][3], yl[kk*2],yl[kk*2+1]);
            mma_tf32(xlh0,xlh1,xlh2,xlh3, al[kk][0],al[kk][1],al[kk][2],al[kk][3], xh[kk*2],xh[kk*2+1]);
            mma_tf32(ylh0,ylh1,ylh2,ylh3, al[kk][0],al[kk][1],al[kk][2],al[kk][3], yh[kk*2],yh[kk*2+1]);
        }
        {
            float d0 = xhh0 + (xhl0 + xlh0);
            float d1 = xhh1 + (xhl1 + xlh1);
            float d2 = xhh2 + (xhl2 + xlh2);
            float d3 = xhh3 + (xhl3 + xlh3);
            const int ce = c0 + 2*qc;
            float cnE = smf[O_CN2 + ce], cnO = smf[O_CN2 + ce + 1];
            float e;
            e = cnE - d0; if (e < bestA) { bestA = e; biA = ce; }
            e = cnO - d1; if (e < bestA) { bestA = e; biA = ce + 1; }
            e = cnE - d2; if (e < bestB) { bestB = e; biB = ce; }
            e = cnO - d3; if (e < bestB) { bestB = e; biB = ce + 1; }
        }
        {
            float d0 = yhh0 + (yhl0 + ylh0);
            float d1 = yhh1 + (yhl1 + ylh1);
            float d2 = yhh2 + (yhl2 + ylh2);
            float d3 = yhh3 + (yhl3 + ylh3);
            const int ce = c1 + 2*qc;
            float cnE = smf[O_CN2 + ce], cnO = smf[O_CN2 + ce + 1];
            float e;
            e = cnE - d0; if (e < bestA) { bestA = e; biA = ce; }
            e = cnO - d1; if (e < bestA) { bestA = e; biA = ce + 1; }
            e = cnE - d2; if (e < bestB) { bestB = e; biB = ce; }
            e = cnO - d3; if (e < bestB) { bestB = e; biB = ce + 1; }
        }
    }
    #pragma unroll
    for (int off = 1; off <= 2; off <<= 1) {
        float eA = __shfl_xor_sync(0xffffffffu, bestA, off);
        int   iA = __shfl_xor_sync(0xffffffffu, biA, off);
        if (eA < bestA || (eA == bestA && iA < biA)) { bestA = eA; biA = iA; }
        float eB = __shfl_xor_sync(0xffffffffu, bestB, off);
        int   iB = __shfl_xor_sync(0xffffffffu, biB, off);
        if (eB < bestB || (eB == bestB && iB < biB)) { bestB = eB; biB = iB; }
    }
    int* s_ri = (int*)&smf[O_RI];
    if (qc == 0) {
        s_ri[m0 + qr]     = biA;
        s_ri[m0 + 8 + qr] = biB;
    }
    __syncthreads();

    float cl = 0.f;
    if (tid < 256) {
        int fi = s_ri[tid];
        out_idx[P0 + tid] = (float)fi;
        #pragma unroll
        for (int d = 0; d < DIM; d++) {
            float zv = smf[O_ZH + tid*ST36 + d] + smf[O_ZL + tid*ST36 + d];
            float cv = smf[O_CBH + fi*ST36 + d] + smf[O_CBL + fi*ST36 + d];
            float df = cv - zv;
            cl = fmaf(df, df, cl);
        }
    }
    #pragma unroll
    for (int off = 16; off; off >>= 1) cl += __shfl_down_sync(0xffffffffu, cl, off);
    __shared__ float wsum[16];
    if ((tid & 31) == 0) wsum[tid >> 5] = (tid < 256) ? cl : 0.f;
    __syncthreads();
    if (tid == 0) {
        float s = 0.f;
        #pragma unroll
        for (int ww = 0; ww < 16; ww++) s += wsum[ww];
        atomicAdd(&g_loss, (double)s);
    }
}

// ---------------------------------------------------------------------------
// k4: (R9 version) nearest-upsample2(h2) + conv3 (32->16) + gelu
// grid (4, HALFB); 32x32 tile; 2x2/thread; batch offset b0
// ---------------------------------------------------------------------------
#define K4_SMEM ((32*18*18 + 32*9*16 + 16)*4)
__global__ __launch_bounds__(256) void k4(const float* __restrict__ w3,
                                          const float* __restrict__ b3, int b0) {
    extern __shared__ __align__(16) float sm4[];
    float* s_h = sm4;
    float* s_w = sm4 + 32*18*18;     // [ic][t][oc]
    float* s_b = s_w + 32*9*16;
    const int b = blockIdx.y + b0;
    const int tile = blockIdx.x;
    const int oy = (tile >> 1) * 32, ox = (tile & 1) * 32;
    const int hy0 = oy/2 - 1, hx0 = ox/2 - 1;
    const int tid = threadIdx.y*16 + threadIdx.x;
    for (int i = tid; i < 16*32*9; i += 256) {
        int o = i / 288; int rem = i - o*288; int ic = rem / 9; int t = rem - ic*9;
        s_w[(ic*9 + t)*16 + o] = w3[i];
    }
    if (tid < 16) s_b[tid] = b3[tid];
    for (int i = tid; i < 32*18*18; i += 256) {
        int ic = i / 324;
        int rem = i - ic*324;
        int r = rem / 18, c = rem - r*18;
        int hy = hy0 + r, hx = hx0 + c;
        float v = 0.f;
        if ((unsigned)hy < 32u && (unsigned)hx < 32u)
            v = g_h2[((b*32+ic)*32 + hy)*32 + hx];
        s_h[i] = v;
    }
    __syncthreads();
    const int ty = threadIdx.y, tx = threadIdx.x;
    const int y0 = oy + 2*ty, x0 = ox + 2*tx;
    const int map[4] = {0, 1, 1, 2};
    u64 acc[8][4];
    #pragma unroll
    for (int op = 0; op < 8; op++)
        #pragma unroll
        for (int q = 0; q < 4; q++) acc[op][q] = 0ull;
    #pragma unroll 1
    for (int ic = 0; ic < 32; ic++) {
        u64 vp[3][3];
        #pragma unroll
        for (int a = 0; a < 3; a++)
            #pragma unroll
            for (int c = 0; c < 3; c++) {
                float v = s_h[(ic*18 + ty + a)*18 + tx + c];
                vp[a][c] = pk2(v, v);
            }
        #pragma unroll
        for (int t = 0; t < 9; t++) {
            int ky = t / 3, kx = t - ky*3;
            const float* wp = &s_w[(ic*9 + t)*16];
            ulonglong2 wA = *(const ulonglong2*)&wp[0];
            ulonglong2 wB = *(const ulonglong2*)&wp[4];
            ulonglong2 wC = *(const ulonglong2*)&wp[8];
            ulonglong2 wD = *(const ulonglong2*)&wp[12];
            u64 wv[8] = {wA.x, wA.y, wB.x, wB.y, wC.x, wC.y, wD.x, wD.y};
            #pragma unroll
            for (int op = 0; op < 8; op++)
                #pragma unroll
                for (int dy = 0; dy < 2; dy++)
                    #pragma unroll
                    for (int dx = 0; dx < 2; dx++)
                        acc[op][dy*2+dx] = ffma2(vp[map[dy+ky]][map[dx+kx]], wv[op], acc[op][dy*2+dx]);
        }
    }
    #pragma unroll
    for (int op = 0; op < 8; op++) {
        int oc = op*2;
        float blo = s_b[oc], bhi = s_b[oc+1];
        #pragma unroll
        for (int dy = 0; dy < 2; dy++)
            #pragma unroll
            for (int dx = 0; dx < 2; dx++) {
                float lo, hi;
                upk2(acc[op][dy*2+dx], lo, hi);
                g_g[((b*16+oc+0)*64 + (y0+dy))*64 + (x0+dx)] = gelu_exact(lo + blo);
                g_g[((b*16+oc+1)*64 + (y0+dy))*64 + (x0+dx)] = gelu_exact(hi + bhi);
            }
    }
}

// ---------------------------------------------------------------------------
// k5: nearest-upsample2(g) + conv4 (16->1, 3x3 SAME) + clip
// px-paired f32x2: lane pair = (x0, x0+1); weights duplicated in smem pairs.
// Per-lane fmaf sequence identical to scalar version -> bit-identical output.
// grid (16, HALFB); batch offset b0
// ---------------------------------------------------------------------------
__global__ __launch_bounds__(256) void k5(const float* __restrict__ w4,
                                          const float* __restrict__ b4,
                                          float* __restrict__ out, int b0) {
    __shared__ float s_g[16*18*18];
    __shared__ __align__(8) float s_w2[144*2];
    __shared__ float s_bb[1];
    const int b = blockIdx.y + b0;
    const int tile = blockIdx.x;
    const int oy = (tile >> 2) * 32, ox = (tile & 3) * 32;
    const int gy0 = oy/2 - 1, gx0 = ox/2 - 1;
    const int tid = threadIdx.y*16 + threadIdx.x;
    if (tid < 144) { float wv = w4[tid]; s_w2[tid*2] = wv; s_w2[tid*2+1] = wv; }
    if (tid == 0) s_bb[0] = b4[0];
    for (int i = tid; i < 16*18*18; i += 256) {
        int ic = i / 324;
        int rem = i - ic*324;
        int r = rem / 18, c = rem - r*18;
        int gy = gy0 + r, gx = gx0 + c;
        float v = 0.f;
        if ((unsigned)gy < 64u && (unsigned)gx < 64u)
            v = g_g[((b*16+ic)*64 + gy)*64 + gx];
        s_g[i] = v;
    }
    __syncthreads();
    const int ty = threadIdx.y, tx = threadIdx.x;
    const int y0 = oy + 2*ty, x0 = ox + 2*tx;
    u64 acc2[2] = {0ull, 0ull};    // rows dy=0,1; lanes = (dx=0, dx=1)
    #pragma unroll 1
    for (int ic = 0; ic < 16; ic++) {
        float v[3][3];
        #pragma unroll
        for (int a = 0; a < 3; a++)
            #pragma unroll
            for (int c = 0; c < 3; c++)
                v[a][c] = s_g[(ic*18 + ty + a)*18 + tx + c];
        // packed column operands: kx -> (map[kx], map[kx+1]) = (0,1),(1,1),(1,2)
        u64 p[3][3];
        #pragma unroll
        for (int a = 0; a < 3; a++) {
            p[a][0] = pk2(v[a][0], v[a][1]);
            p[a][1] = pk2(v[a][1], v[a][1]);
            p[a][2] = pk2(v[a][1], v[a][2]);
        }
        const float* w2p = &s_w2[ic*18];
        #pragma unroll
        for (int t = 0; t < 9; t++) {
            int ky = t / 3, kx = t - ky*3;
            u64 wt2 = *(const u64*)&w2p[t*2];
            // dy=0 row map[ky]; dy=1 row map[ky+1]
            int r0i = (ky == 0) ? 0 : 1;          // map[ky]   for ky=0,1,2 -> 0,1,1
            int r1i = (ky == 2) ? 2 : 1;          // map[ky+1] for ky=0,1,2 -> 1,1,2
            acc2[0] = ffma2(p[r0i][kx], wt2, acc2[0]);
            acc2[1] = ffma2(p[r1i][kx], wt2, acc2[1]);
        }
    }
    float bb = s_bb[0];
    #pragma unroll
    for (int dy = 0; dy < 2; dy++) {
        float lo, hi;
        upk2(acc2[dy], lo, hi);
        out[(b*H0 + (y0+dy))*W0 + (x0+0)] = fminf(fmaxf(lo + bb, -1.f), 1.f);
        out[(b*H0 + (y0+dy))*W0 + (x0+1)] = fminf(fmaxf(hi + bb, -1.f), 1.f);
    }
}

// ---------------------------------------------------------------------------
__global__ void k_zero() { if (threadIdx.x == 0) g_loss = 0.0; }
__global__ void k_fin(float* __restrict__ out_loss) {
    if (threadIdx.x == 0)
        out_loss[0] = (float)(g_loss / (double)(BATCH * 1024 * DIM));
}

// ---------------------------------------------------------------------------
// Batch-split dual-stream pipeline: two independent serial chains (halves of
// the batch) interleave across streams -> cross-stream tail packing and
// tensor(k3m)/fma(k2,k4,k5) wave-level mixing. Writes disjoint per half.
// ---------------------------------------------------------------------------
extern "C" void kernel_launch(void* const* d_in, const int* in_sizes, int n_in,
                              void* d_out, int out_size) {
    const float* x  = (const float*)d_in[0];
    const float* w1 = (const float*)d_in[1];
    const float* b1 = (const float*)d_in[2];
    const float* w2 = (const float*)d_in[3];
    const float* b2 = (const float*)d_in[4];
    const float* cb = (const float*)d_in[5];
    const float* w3 = (const float*)d_in[6];
    const float* b3 = (const float*)d_in[7];
    const float* w4 = (const float*)d_in[8];
    const float* b4 = (const float*)d_in[9];

    float* out      = (float*)d_out;
    float* out_idx  = out + BATCH*H0*W0;          // 2,097,152
    float* out_loss = out_idx + BATCH*H2*H2;      // +131,072

    cudaFuncSetAttribute(k2,  cudaFuncAttributeMaxDynamicSharedMemorySize, K2_SMEM);
    cudaFuncSetAttribute(k3m, cudaFuncAttributeMaxDynamicSharedMemorySize, K3M_SMEM);
    cudaFuncSetAttribute(k4,  cudaFuncAttributeMaxDynamicSharedMemorySize, K4_SMEM);

    cudaStream_t sB;
    cudaEvent_t evZ, evB;
    cudaStreamCreateWithFlags(&sB, cudaStreamNonBlocking);
    cudaEventCreateWithFlags(&evZ, cudaEventDisableTiming);
    cudaEventCreateWithFlags(&evB, cudaEventDisableTiming);

    k_zero<<<1, 32>>>();
    cudaEventRecord(evZ, 0);
    cudaStreamWaitEvent(sB, evZ, 0);

    // half A on default stream
    k1<<<dim3(8, HALFB), 256>>>(x, w1, b1, 0);
    k2<<<dim3(4, HALFB), 256, K2_SMEM>>>(w2, b2, 0);
    k3m<<<256, 512, K3M_SMEM>>>(cb, out_idx, 0);
    k4<<<dim3(4, HALFB), dim3(16,16), K4_SMEM>>>(w3, b3, 0);
    k5<<<dim3(16, HALFB), dim3(16,16)>>>(w4, b4, out, 0);

    // half B on side stream
    k1<<<dim3(8, HALFB), 256, 0, sB>>>(x, w1, b1, HALFB);
    k2<<<dim3(4, HALFB), 256, K2_SMEM, sB>>>(w2, b2, HALFB);
    k3m<<<256, 512, K3M_SMEM, sB>>>(cb, out_idx, HALFB*1024);
    k4<<<dim3(4, HALFB), dim3(16,16), K4_SMEM, sB>>>(w3, b3, HALFB);
    k5<<<dim3(16, HALFB), dim3(16,16), 0, sB>>>(w4, b4, out, HALFB);
    cudaEventRecord(evB, sB);

    cudaStreamWaitEvent(0, evB, 0);
    k_fin<<<1, 32>>>(out_loss);
}